// round 15
// baseline (speedup 1.0000x reference)
#include <cuda_runtime.h>
#include <cuda_fp16.h>
#include <math.h>
#include <stdint.h>

// ===========================================================================
// TinyMoE, base-ISA tensor ops (mma.sync fp16 / ldmatrix / cp.async).
// R15: R14 base; ONE change: gateup warp tiles 64x32 per matrix (8 warps,
//      256 thr) -> 4.0 MMA/ldsm, -35% smem reads (smem-port-bound per R14 ncu).
// ===========================================================================

#define T_TOK 4096
#define HD    1024
#define NE    8
#define EPITCH 4096

using f16 = __half;

// ---------------- device scratch -------------------------------------------
__device__ f16   g_xc   [(size_t)T_TOK * 1024];
__device__ f16   g_wsg  [(size_t)1024 * 1024];
__device__ f16   g_wsu  [(size_t)1024 * 1024];
__device__ f16   g_wsd  [(size_t)1024 * 1024];
__device__ f16   g_weg  [(size_t)NE * 1024 * 1024];
__device__ f16   g_weu  [(size_t)NE * 1024 * 1024];
__device__ f16   g_wed  [(size_t)NE * 1024 * 1024];
__device__ f16   g_hid_s[(size_t)T_TOK * 1024];
__device__ f16   g_hid_r[(size_t)NE * EPITCH * 1024];
__device__ float g_rout [(size_t)NE * EPITCH * 1024];
__device__ int   g_cnt[NE];
__device__ int   g_tok[NE][T_TOK];
__device__ int   g_sel_e[T_TOK * 2];
__device__ int   g_sel_p[T_TOK * 2];
__device__ float g_sel_w[T_TOK * 2];

// ---------------- asm helpers ----------------------------------------------
__device__ __forceinline__ uint32_t s2u(const void* p) {
    uint32_t a;
    asm("{ .reg .u64 t; cvta.to.shared.u64 t, %1; cvt.u32.u64 %0, t; }" : "=r"(a) : "l"(p));
    return a;
}
__device__ __forceinline__ void cp16(uint32_t dst, const void* src) {
    asm volatile("cp.async.cg.shared.global [%0], [%1], 16;" :: "r"(dst), "l"(src));
}
__device__ __forceinline__ void cp_commit() { asm volatile("cp.async.commit_group;"); }
__device__ __forceinline__ void cp_wait2()  { asm volatile("cp.async.wait_group 2;"); }
__device__ __forceinline__ void ldsm4(uint32_t* r, uint32_t addr) {
    asm volatile("ldmatrix.sync.aligned.m8n8.x4.shared.b16 {%0,%1,%2,%3}, [%4];"
        : "=r"(r[0]), "=r"(r[1]), "=r"(r[2]), "=r"(r[3]) : "r"(addr));
}
__device__ __forceinline__ void mma_f16(float* c, const uint32_t* a, const uint32_t* b) {
    asm volatile(
        "mma.sync.aligned.m16n8k16.row.col.f32.f16.f16.f32 "
        "{%0,%1,%2,%3}, {%4,%5,%6,%7}, {%8,%9}, {%0,%1,%2,%3};"
        : "+f"(c[0]), "+f"(c[1]), "+f"(c[2]), "+f"(c[3])
        : "r"(a[0]), "r"(a[1]), "r"(a[2]), "r"(a[3]), "r"(b[0]), "r"(b[1]));
}
__device__ __forceinline__ uint32_t packh2(float a, float b) {
    f16 h0 = __float2half_rn(a), h1 = __float2half_rn(b);
    return (uint32_t)*(uint16_t*)&h0 | ((uint32_t)*(uint16_t*)&h1 << 16);
}

// ---------------------------------------------------------------------------
// convw: smem-free transpose-convert; block (0,0,0) zeroes g_cnt
// ---------------------------------------------------------------------------
__global__ void __launch_bounds__(256)
k_convw(const float* __restrict__ SG, const float* __restrict__ SU,
        const float* __restrict__ SD, const float* __restrict__ EG,
        const float* __restrict__ EU, const float* __restrict__ ED,
        f16* __restrict__ wsg, f16* __restrict__ wsu, f16* __restrict__ wsd,
        f16* __restrict__ weg, f16* __restrict__ weu, f16* __restrict__ wed)
{
    if (blockIdx.x == 0 && blockIdx.y == 0 && blockIdx.z == 0 && threadIdx.x < NE)
        g_cnt[threadIdx.x] = 0;

    const int z = blockIdx.z;
    const float* src;
    f16* dst;
    if      (z == 0) { src = SG; dst = wsg; }
    else if (z == 1) { src = SU; dst = wsu; }
    else if (z == 2) { src = SD; dst = wsd; }
    else if (z < 11) { src = EG + (size_t)(z - 3)  * 1048576; dst = weg + (size_t)(z - 3)  * 1048576; }
    else if (z < 19) { src = EU + (size_t)(z - 11) * 1048576; dst = weu + (size_t)(z - 11) * 1048576; }
    else             { src = ED + (size_t)(z - 19) * 1048576; dst = wed + (size_t)(z - 19) * 1048576; }

    const int n  = blockIdx.x * 256 + threadIdx.x;
    const int k0 = blockIdx.y * 16;
    float v[16];
#pragma unroll
    for (int kk = 0; kk < 16; kk++)
        v[kk] = src[(size_t)(k0 + kk) * 1024 + n];
    uint4 a, b;
    a.x = packh2(v[0],  v[1]);  a.y = packh2(v[2],  v[3]);
    a.z = packh2(v[4],  v[5]);  a.w = packh2(v[6],  v[7]);
    b.x = packh2(v[8],  v[9]);  b.y = packh2(v[10], v[11]);
    b.z = packh2(v[12], v[13]); b.w = packh2(v[14], v[15]);
    f16* drow = dst + (size_t)n * 1024 + k0;
    *reinterpret_cast<uint4*>(drow)     = a;
    *reinterpret_cast<uint4*>(drow + 8) = b;
}

// ---------------------------------------------------------------------------
// router + fused convx
// ---------------------------------------------------------------------------
__global__ void k_router(const float* __restrict__ X, const float* __restrict__ RW) {
    const int t = (blockIdx.x * blockDim.x + threadIdx.x) >> 5;
    const int lane = threadIdx.x & 31;
    if (t >= T_TOK) return;
    const float4* xr = reinterpret_cast<const float4*>(X + (size_t)t * HD);
    float acc[NE];
#pragma unroll
    for (int e = 0; e < NE; e++) acc[e] = 0.f;
#pragma unroll
    for (int i = 0; i < 8; i++) {
        const float4 xv = xr[i * 32 + lane];
        const uint2 hp = make_uint2(packh2(xv.x, xv.y), packh2(xv.z, xv.w));
        *reinterpret_cast<uint2*>(g_xc + (size_t)t * HD + (i * 32 + lane) * 4) = hp;
#pragma unroll
        for (int e = 0; e < NE; e++) {
            const float4 wv = *reinterpret_cast<const float4*>(
                RW + (size_t)e * HD + i * 128 + lane * 4);
            acc[e] += xv.x * wv.x + xv.y * wv.y + xv.z * wv.z + xv.w * wv.w;
        }
    }
#pragma unroll
    for (int e = 0; e < NE; e++)
#pragma unroll
        for (int off = 16; off > 0; off >>= 1)
            acc[e] += __shfl_down_sync(0xffffffffu, acc[e], off);
    if (lane == 0) {
        float m = acc[0];
#pragma unroll
        for (int e = 1; e < NE; e++) m = fmaxf(m, acc[e]);
        float p[NE], s = 0.f;
#pragma unroll
        for (int e = 0; e < NE; e++) { p[e] = expf(acc[e] - m); s += p[e]; }
        const float inv = 1.f / s;
#pragma unroll
        for (int e = 0; e < NE; e++) p[e] *= inv;
        int i1 = 0; float b1 = p[0];
#pragma unroll
        for (int e = 1; e < NE; e++) if (p[e] > b1) { b1 = p[e]; i1 = e; }
        int i2 = -1; float b2 = -1.f;
#pragma unroll
        for (int e = 0; e < NE; e++) if (e != i1 && p[e] > b2) { b2 = p[e]; i2 = e; }
        int pos = atomicAdd(&g_cnt[i1], 1);
        g_tok[i1][pos] = t;
        g_sel_e[t * 2] = i1; g_sel_p[t * 2] = pos; g_sel_w[t * 2] = b1;
        pos = atomicAdd(&g_cnt[i2], 1);
        g_tok[i2][pos] = t;
        g_sel_e[t * 2 + 1] = i2; g_sel_p[t * 2 + 1] = pos; g_sel_w[t * 2 + 1] = b2;
    }
}

// ---------------------------------------------------------------------------
// Fused gate+up GEMM + SwiGLU. 256 threads, 8 warps = 2m x 4n of
// 64m x 32n warp tiles per matrix (4.0 MMA/ldsm). BK=64, 16 iters, 3 stages.
// ---------------------------------------------------------------------------
#define GU_STG   49152
#define GU_SMEM  (3 * GU_STG)

__global__ void __launch_bounds__(256)
k_gateup(const f16* __restrict__ A, const f16* __restrict__ Bg_all,
         const f16* __restrict__ Bu_all, const f16* __restrict__ Beg,
         const f16* __restrict__ Beu, f16* __restrict__ Hs, f16* __restrict__ Hr)
{
    extern __shared__ char smraw[];
    const uint32_t smu = s2u(smraw);
    const int tid = threadIdx.x;
    const int bn = blockIdx.x * 128;
    const int bm = blockIdx.y * 128;
    const int z = blockIdx.z;

    const f16 *Bg, *Bu;
    f16* Hout;
    const int* toks = nullptr;
    int cnt = 0;
    if (z == 0) {
        Bg = Bg_all; Bu = Bu_all; Hout = Hs;
    } else {
        const int e = z - 1;
        cnt = g_cnt[e];
        if (bm >= cnt) return;
        toks = g_tok[e];
        Bg = Beg + (size_t)e * 1048576;
        Bu = Beu + (size_t)e * 1048576;
        Hout = Hr + (size_t)e * EPITCH * 1024;
    }

    // load mapping: 256 threads cover 128 rows x 8 chunks per tile via 4 iters
    const int lr = tid >> 3;        // 0..31
    const int lc = tid & 7;
    const int coff = lc * 8;

    const f16 *arp[4], *bgp[4], *bup[4];
    uint32_t dA[4];
#pragma unroll
    for (int i = 0; i < 4; i++) {
        const int r = lr + 32 * i;
        int arow;
        if (z != 0) {
            const int slot = bm + r;
            arow = toks[slot < cnt - 1 ? slot : cnt - 1];
        } else {
            arow = bm + r;
        }
        arp[i] = A  + (size_t)arow * 1024 + coff;
        bgp[i] = Bg + (size_t)(bn + r) * 1024 + coff;
        bup[i] = Bu + (size_t)(bn + r) * 1024 + coff;
        dA[i] = (uint32_t)(r * 128 + ((lc ^ (r & 7)) << 4));
    }

    const int lane = tid & 31, w = tid >> 5;
    const int m0 = (w >> 2) * 64, n0 = (w & 3) * 32;

    float accG[4][4][4], accU[4][4][4];
#pragma unroll
    for (int mf = 0; mf < 4; mf++)
#pragma unroll
        for (int nf = 0; nf < 4; nf++)
#pragma unroll
            for (int j = 0; j < 4; j++) { accG[mf][nf][j] = 0.f; accU[mf][nf][j] = 0.f; }

#pragma unroll
    for (int st = 0; st < 2; st++) {
        const uint32_t sa = smu + st * GU_STG;
        const int kb = st * 64;
#pragma unroll
        for (int i = 0; i < 4; i++) {
            cp16(sa + dA[i],          arp[i] + kb);
            cp16(sa + 16384u + dA[i], bgp[i] + kb);
            cp16(sa + 32768u + dA[i], bup[i] + kb);
        }
        cp_commit();
    }

    const int ar_ = lane & 15;
    const int ac_ = lane >> 4;
    const int br_ = (lane & 7) + ((lane >> 4) << 3);
    const int bc_ = (lane >> 3) & 1;

    int stw = 2;
    for (int it = 0; it < 16; ++it) {
        if (it + 2 < 16) {
            const uint32_t sa = smu + stw * GU_STG;
            const int kb = (it + 2) * 64;
#pragma unroll
            for (int i = 0; i < 4; i++) {
                cp16(sa + dA[i],          arp[i] + kb);
                cp16(sa + 16384u + dA[i], bgp[i] + kb);
                cp16(sa + 32768u + dA[i], bup[i] + kb);
            }
            stw = (stw + 1) == 3 ? 0 : stw + 1;
        }
        cp_commit();
        cp_wait2();
        __syncthreads();

        const uint32_t sa = smu + (it % 3) * GU_STG;
        const uint32_t sg = sa + 16384u, su = sa + 32768u;
#pragma unroll
        for (int s = 0; s < 4; s++) {
            uint32_t av[4][4];
#pragma unroll
            for (int mf = 0; mf < 4; mf++) {
                const int r = m0 + mf * 16 + ar_;
                const int c = s * 2 + ac_;
                ldsm4(av[mf], sa + r * 128 + ((c ^ (r & 7)) << 4));
            }
            {
                uint32_t bv[2][4];
#pragma unroll
                for (int bi = 0; bi < 2; bi++) {
                    const int nr = n0 + bi * 16 + br_;
                    const int c = s * 2 + bc_;
                    ldsm4(bv[bi], sg + nr * 128 + ((c ^ (nr & 7)) << 4));
                }
#pragma unroll
                for (int mf = 0; mf < 4; mf++)
#pragma unroll
                    for (int nf = 0; nf < 4; nf++)
                        mma_f16(accG[mf][nf], av[mf], &bv[nf >> 1][(nf & 1) * 2]);
            }
            {
                uint32_t bv[2][4];
#pragma unroll
                for (int bi = 0; bi < 2; bi++) {
                    const int nr = n0 + bi * 16 + br_;
                    const int c = s * 2 + bc_;
                    ldsm4(bv[bi], su + nr * 128 + ((c ^ (nr & 7)) << 4));
                }
#pragma unroll
                for (int mf = 0; mf < 4; mf++)
#pragma unroll
                    for (int nf = 0; nf < 4; nf++)
                        mma_f16(accU[mf][nf], av[mf], &bv[nf >> 1][(nf & 1) * 2]);
            }
        }
        __syncthreads();
    }

    const int mr = lane >> 2, nc2 = (lane & 3) * 2;
#pragma unroll
    for (int mf = 0; mf < 4; mf++)
#pragma unroll
        for (int nf = 0; nf < 4; nf++)
#pragma unroll
            for (int h = 0; h < 2; h++) {
                const int rl = m0 + mf * 16 + mr + h * 8;
                const int col = bn + n0 + nf * 8 + nc2;
                const float g0 = accG[mf][nf][h * 2], g1 = accG[mf][nf][h * 2 + 1];
                const float u0 = accU[mf][nf][h * 2], u1 = accU[mf][nf][h * 2 + 1];
                const float v0 = u0 / (1.f + __expf(-g0));
                const float v1 = u1 / (1.f + __expf(-g1));
                *reinterpret_cast<uint32_t*>(Hout + (size_t)(bm + rl) * 1024 + col) =
                    packh2(v0, v1);
            }
}

// ---------------------------------------------------------------------------
// Down GEMM (R14, unchanged). 256 threads, warp tile 32x64, BK=64, 3 stages.
// ---------------------------------------------------------------------------
#define DN_STG   32768
#define DN_SMEM  (3 * DN_STG)

__global__ void __launch_bounds__(256)
k_down(const f16* __restrict__ As, const f16* __restrict__ Ar,
       const f16* __restrict__ Bs, const f16* __restrict__ Be,
       const float* __restrict__ X, float* __restrict__ out, float* __restrict__ rout)
{
    extern __shared__ char smraw[];
    const uint32_t smu = s2u(smraw);
    const int tid = threadIdx.x;
    const int bn = blockIdx.x * 128;
    const int bm = blockIdx.y * 128;
    const int z = blockIdx.z;

    const f16 *A, *B;
    size_t obase = 0;
    if (z == 0) {
        A = As; B = Bs;
    } else {
        const int e = z - 1;
        if (bm >= g_cnt[e]) return;
        obase = (size_t)e * EPITCH;
        A = Ar + obase * 1024;
        B = Be + (size_t)e * 1048576;
    }

    const int lr = tid >> 3;
    const int lc = tid & 7;
    const int coff = lc * 8;

    const f16 *arp[4], *brp[4];
    uint32_t dA[4], dB[4];
#pragma unroll
    for (int i = 0; i < 4; i++) {
        const int r = lr + 32 * i;
        arp[i] = A + (size_t)(bm + r) * 1024 + coff;
        brp[i] = B + (size_t)(bn + r) * 1024 + coff;
        const uint32_t o = (uint32_t)(r * 128 + ((lc ^ (r & 7)) << 4));
        dA[i] = o; dB[i] = 16384u + o;
    }

    const int lane = tid & 31, w = tid >> 5;
    const int m0 = (w & 3) * 32, n0 = (w >> 2) * 64;

    float acc[2][8][4];
#pragma unroll
    for (int mf = 0; mf < 2; mf++)
#pragma unroll
        for (int nf = 0; nf < 8; nf++)
#pragma unroll
            for (int j = 0; j < 4; j++) acc[mf][nf][j] = 0.f;

#pragma unroll
    for (int st = 0; st < 2; st++) {
        const uint32_t sa = smu + st * DN_STG;
        const int kb = st * 64;
#pragma unroll
        for (int i = 0; i < 4; i++) { cp16(sa + dA[i], arp[i] + kb); cp16(sa + dB[i], brp[i] + kb); }
        cp_commit();
    }

    const int ar_ = lane & 15;
    const int ac_ = lane >> 4;
    const int br_ = (lane & 7) + ((lane >> 4) << 3);
    const int bc_ = (lane >> 3) & 1;

    int stw = 2;
    for (int it = 0; it < 16; ++it) {
        if (it + 2 < 16) {
            const uint32_t sa = smu + stw * DN_STG;
            const int kb = (it + 2) * 64;
#pragma unroll
            for (int i = 0; i < 4; i++) { cp16(sa + dA[i], arp[i] + kb); cp16(sa + dB[i], brp[i] + kb); }
            stw = (stw + 1) == 3 ? 0 : stw + 1;
        }
        cp_commit();
        cp_wait2();
        __syncthreads();

        const uint32_t sa = smu + (it % 3) * DN_STG;
        const uint32_t sb = sa + 16384u;
#pragma unroll
        for (int s = 0; s < 4; s++) {
            uint32_t av[2][4], bv[4][4];
#pragma unroll
            for (int mf = 0; mf < 2; mf++) {
                const int r = m0 + mf * 16 + ar_;
                const int c = s * 2 + ac_;
                ldsm4(av[mf], sa + r * 128 + ((c ^ (r & 7)) << 4));
            }
#pragma unroll
            for (int bi = 0; bi < 4; bi++) {
                const int nr = n0 + bi * 16 + br_;
                const int c = s * 2 + bc_;
                ldsm4(bv[bi], sb + nr * 128 + ((c ^ (nr & 7)) << 4));
            }
#pragma unroll
            for (int mf = 0; mf < 2; mf++)
#pragma unroll
                for (int nf = 0; nf < 8; nf++)
                    mma_f16(acc[mf][nf], av[mf], &bv[nf >> 1][(nf & 1) * 2]);
        }
        __syncthreads();
    }

    const int mr = lane >> 2, nc2 = (lane & 3) * 2;
#pragma unroll
    for (int mf = 0; mf < 2; mf++)
#pragma unroll
        for (int nf = 0; nf < 8; nf++)
#pragma unroll
            for (int h = 0; h < 2; h++) {
                const int rl = m0 + mf * 16 + mr + h * 8;
                const int col = bn + n0 + nf * 8 + nc2;
                const float c0 = acc[mf][nf][h * 2], c1 = acc[mf][nf][h * 2 + 1];
                if (z == 0) {
                    const int t = bm + rl;
                    const float2 rv = *reinterpret_cast<const float2*>(X + (size_t)t * 1024 + col);
                    float2 v = make_float2(rv.x + c0, rv.y + c1);
                    *reinterpret_cast<float2*>(out + (size_t)t * 1024 + col) = v;
                } else {
                    float2 v = make_float2(c0, c1);
                    *reinterpret_cast<float2*>(rout + (obase + bm + rl) * 1024 + col) = v;
                }
            }
}

// ---------------------------------------------------------------------------
// combine
// ---------------------------------------------------------------------------
__global__ void k_combine(float* __restrict__ out) {
    const int t = blockIdx.x;
    const int e1 = g_sel_e[t * 2],     p1 = g_sel_p[t * 2];
    const int e2 = g_sel_e[t * 2 + 1], p2 = g_sel_p[t * 2 + 1];
    const float w1 = g_sel_w[t * 2], w2 = g_sel_w[t * 2 + 1];
    const float* r1 = g_rout + ((size_t)e1 * EPITCH + p1) * 1024;
    const float* r2 = g_rout + ((size_t)e2 * EPITCH + p2) * 1024;
    float* o = out + (size_t)t * 1024;
#pragma unroll
    for (int k = 0; k < 2; k++) {
        const int j = (threadIdx.x + k * 128) * 4;
        const float4 a = *(const float4*)(r1 + j);
        const float4 b = *(const float4*)(r2 + j);
        float4 v = *(float4*)(o + j);
        v.x += w1 * a.x + w2 * b.x; v.y += w1 * a.y + w2 * b.y;
        v.z += w1 * a.z + w2 * b.z; v.w += w1 * a.w + w2 * b.w;
        *(float4*)(o + j) = v;
    }
}

// ---------------------------------------------------------------------------
// launch
// ---------------------------------------------------------------------------
extern "C" void kernel_launch(void* const* d_in, const int* in_sizes, int n_in,
                              void* d_out, int out_size)
{
    const float* X  = (const float*)d_in[0];
    const float* RW = (const float*)d_in[1];
    const float* SG = (const float*)d_in[2];
    const float* SU = (const float*)d_in[3];
    const float* SD = (const float*)d_in[4];
    const float* EG = (const float*)d_in[5];
    const float* EU = (const float*)d_in[6];
    const float* ED = (const float*)d_in[7];
    float* out = (float*)d_out;

    static bool once = false;
    if (!once) {
        cudaFuncSetAttribute(k_gateup, cudaFuncAttributeMaxDynamicSharedMemorySize, GU_SMEM);
        cudaFuncSetAttribute(k_down,   cudaFuncAttributeMaxDynamicSharedMemorySize, DN_SMEM);
        once = true;
    }

    f16 *xc, *wsg, *wsu, *wsd, *weg, *weu, *wed, *hids, *hidr;
    float *rout;
    cudaGetSymbolAddress((void**)&xc,   g_xc);
    cudaGetSymbolAddress((void**)&wsg,  g_wsg);
    cudaGetSymbolAddress((void**)&wsu,  g_wsu);
    cudaGetSymbolAddress((void**)&wsd,  g_wsd);
    cudaGetSymbolAddress((void**)&weg,  g_weg);
    cudaGetSymbolAddress((void**)&weu,  g_weu);
    cudaGetSymbolAddress((void**)&wed,  g_wed);
    cudaGetSymbolAddress((void**)&hids, g_hid_s);
    cudaGetSymbolAddress((void**)&hidr, g_hid_r);
    cudaGetSymbolAddress((void**)&rout, g_rout);

    k_convw<<<dim3(4, 64, 27), 256>>>(SG, SU, SD, EG, EU, ED,
                                      wsg, wsu, wsd, weg, weu, wed);  // zeroes g_cnt
    k_router<<<1024, 128>>>(X, RW);                                   // + convx fused

    k_gateup<<<dim3(8, 32, 9), 256, GU_SMEM>>>(xc, wsg, wsu, weg, weu, hids, hidr);
    k_down  <<<dim3(8, 32, 9), 256, DN_SMEM>>>(hids, hidr, wsd, wed, X, out, rout);

    k_combine<<<T_TOK, 128>>>(out);
}

// round 16
// speedup vs baseline: 1.0112x; 1.0112x over previous
#include <cuda_runtime.h>
#include <cuda_fp16.h>
#include <math.h>
#include <stdint.h>

// ===========================================================================
// TinyMoE, base-ISA tensor ops (mma.sync fp16 / ldmatrix / cp.async).
// R16: R14 base (305us); ONE change: k_down fragment double-buffering
//      (ldsm for k16-step s+1 issued before MMAs of step s -> hide LDSM lat).
// ===========================================================================

#define T_TOK 4096
#define HD    1024
#define NE    8
#define EPITCH 4096

using f16 = __half;

// ---------------- device scratch -------------------------------------------
__device__ f16   g_xc   [(size_t)T_TOK * 1024];
__device__ f16   g_wsg  [(size_t)1024 * 1024];
__device__ f16   g_wsu  [(size_t)1024 * 1024];
__device__ f16   g_wsd  [(size_t)1024 * 1024];
__device__ f16   g_weg  [(size_t)NE * 1024 * 1024];
__device__ f16   g_weu  [(size_t)NE * 1024 * 1024];
__device__ f16   g_wed  [(size_t)NE * 1024 * 1024];
__device__ f16   g_hid_s[(size_t)T_TOK * 1024];
__device__ f16   g_hid_r[(size_t)NE * EPITCH * 1024];
__device__ float g_rout [(size_t)NE * EPITCH * 1024];
__device__ int   g_cnt[NE];
__device__ int   g_tok[NE][T_TOK];
__device__ int   g_sel_e[T_TOK * 2];
__device__ int   g_sel_p[T_TOK * 2];
__device__ float g_sel_w[T_TOK * 2];

// ---------------- asm helpers ----------------------------------------------
__device__ __forceinline__ uint32_t s2u(const void* p) {
    uint32_t a;
    asm("{ .reg .u64 t; cvta.to.shared.u64 t, %1; cvt.u32.u64 %0, t; }" : "=r"(a) : "l"(p));
    return a;
}
__device__ __forceinline__ void cp16(uint32_t dst, const void* src) {
    asm volatile("cp.async.cg.shared.global [%0], [%1], 16;" :: "r"(dst), "l"(src));
}
__device__ __forceinline__ void cp_commit() { asm volatile("cp.async.commit_group;"); }
__device__ __forceinline__ void cp_wait2()  { asm volatile("cp.async.wait_group 2;"); }
__device__ __forceinline__ void ldsm4(uint32_t* r, uint32_t addr) {
    asm volatile("ldmatrix.sync.aligned.m8n8.x4.shared.b16 {%0,%1,%2,%3}, [%4];"
        : "=r"(r[0]), "=r"(r[1]), "=r"(r[2]), "=r"(r[3]) : "r"(addr));
}
__device__ __forceinline__ void mma_f16(float* c, const uint32_t* a, const uint32_t* b) {
    asm volatile(
        "mma.sync.aligned.m16n8k16.row.col.f32.f16.f16.f32 "
        "{%0,%1,%2,%3}, {%4,%5,%6,%7}, {%8,%9}, {%0,%1,%2,%3};"
        : "+f"(c[0]), "+f"(c[1]), "+f"(c[2]), "+f"(c[3])
        : "r"(a[0]), "r"(a[1]), "r"(a[2]), "r"(a[3]), "r"(b[0]), "r"(b[1]));
}
__device__ __forceinline__ uint32_t packh2(float a, float b) {
    f16 h0 = __float2half_rn(a), h1 = __float2half_rn(b);
    return (uint32_t)*(uint16_t*)&h0 | ((uint32_t)*(uint16_t*)&h1 << 16);
}

// ---------------------------------------------------------------------------
// convw: smem-free transpose-convert; block (0,0,0) zeroes g_cnt
// ---------------------------------------------------------------------------
__global__ void __launch_bounds__(256)
k_convw(const float* __restrict__ SG, const float* __restrict__ SU,
        const float* __restrict__ SD, const float* __restrict__ EG,
        const float* __restrict__ EU, const float* __restrict__ ED,
        f16* __restrict__ wsg, f16* __restrict__ wsu, f16* __restrict__ wsd,
        f16* __restrict__ weg, f16* __restrict__ weu, f16* __restrict__ wed)
{
    if (blockIdx.x == 0 && blockIdx.y == 0 && blockIdx.z == 0 && threadIdx.x < NE)
        g_cnt[threadIdx.x] = 0;

    const int z = blockIdx.z;
    const float* src;
    f16* dst;
    if      (z == 0) { src = SG; dst = wsg; }
    else if (z == 1) { src = SU; dst = wsu; }
    else if (z == 2) { src = SD; dst = wsd; }
    else if (z < 11) { src = EG + (size_t)(z - 3)  * 1048576; dst = weg + (size_t)(z - 3)  * 1048576; }
    else if (z < 19) { src = EU + (size_t)(z - 11) * 1048576; dst = weu + (size_t)(z - 11) * 1048576; }
    else             { src = ED + (size_t)(z - 19) * 1048576; dst = wed + (size_t)(z - 19) * 1048576; }

    const int n  = blockIdx.x * 256 + threadIdx.x;
    const int k0 = blockIdx.y * 16;
    float v[16];
#pragma unroll
    for (int kk = 0; kk < 16; kk++)
        v[kk] = src[(size_t)(k0 + kk) * 1024 + n];
    uint4 a, b;
    a.x = packh2(v[0],  v[1]);  a.y = packh2(v[2],  v[3]);
    a.z = packh2(v[4],  v[5]);  a.w = packh2(v[6],  v[7]);
    b.x = packh2(v[8],  v[9]);  b.y = packh2(v[10], v[11]);
    b.z = packh2(v[12], v[13]); b.w = packh2(v[14], v[15]);
    f16* drow = dst + (size_t)n * 1024 + k0;
    *reinterpret_cast<uint4*>(drow)     = a;
    *reinterpret_cast<uint4*>(drow + 8) = b;
}

// ---------------------------------------------------------------------------
// router + fused convx
// ---------------------------------------------------------------------------
__global__ void k_router(const float* __restrict__ X, const float* __restrict__ RW) {
    const int t = (blockIdx.x * blockDim.x + threadIdx.x) >> 5;
    const int lane = threadIdx.x & 31;
    if (t >= T_TOK) return;
    const float4* xr = reinterpret_cast<const float4*>(X + (size_t)t * HD);
    float acc[NE];
#pragma unroll
    for (int e = 0; e < NE; e++) acc[e] = 0.f;
#pragma unroll
    for (int i = 0; i < 8; i++) {
        const float4 xv = xr[i * 32 + lane];
        const uint2 hp = make_uint2(packh2(xv.x, xv.y), packh2(xv.z, xv.w));
        *reinterpret_cast<uint2*>(g_xc + (size_t)t * HD + (i * 32 + lane) * 4) = hp;
#pragma unroll
        for (int e = 0; e < NE; e++) {
            const float4 wv = *reinterpret_cast<const float4*>(
                RW + (size_t)e * HD + i * 128 + lane * 4);
            acc[e] += xv.x * wv.x + xv.y * wv.y + xv.z * wv.z + xv.w * wv.w;
        }
    }
#pragma unroll
    for (int e = 0; e < NE; e++)
#pragma unroll
        for (int off = 16; off > 0; off >>= 1)
            acc[e] += __shfl_down_sync(0xffffffffu, acc[e], off);
    if (lane == 0) {
        float m = acc[0];
#pragma unroll
        for (int e = 1; e < NE; e++) m = fmaxf(m, acc[e]);
        float p[NE], s = 0.f;
#pragma unroll
        for (int e = 0; e < NE; e++) { p[e] = expf(acc[e] - m); s += p[e]; }
        const float inv = 1.f / s;
#pragma unroll
        for (int e = 0; e < NE; e++) p[e] *= inv;
        int i1 = 0; float b1 = p[0];
#pragma unroll
        for (int e = 1; e < NE; e++) if (p[e] > b1) { b1 = p[e]; i1 = e; }
        int i2 = -1; float b2 = -1.f;
#pragma unroll
        for (int e = 0; e < NE; e++) if (e != i1 && p[e] > b2) { b2 = p[e]; i2 = e; }
        int pos = atomicAdd(&g_cnt[i1], 1);
        g_tok[i1][pos] = t;
        g_sel_e[t * 2] = i1; g_sel_p[t * 2] = pos; g_sel_w[t * 2] = b1;
        pos = atomicAdd(&g_cnt[i2], 1);
        g_tok[i2][pos] = t;
        g_sel_e[t * 2 + 1] = i2; g_sel_p[t * 2 + 1] = pos; g_sel_w[t * 2 + 1] = b2;
    }
}

// ---------------------------------------------------------------------------
// Fused gate+up GEMM + SwiGLU (R14). 512 threads, warp tile 32x32 per matrix.
// BK=64, 16 iters, 3-stage pipeline.
// ---------------------------------------------------------------------------
#define GU_STG   49152
#define GU_SMEM  (3 * GU_STG)

__global__ void __launch_bounds__(512)
k_gateup(const f16* __restrict__ A, const f16* __restrict__ Bg_all,
         const f16* __restrict__ Bu_all, const f16* __restrict__ Beg,
         const f16* __restrict__ Beu, f16* __restrict__ Hs, f16* __restrict__ Hr)
{
    extern __shared__ char smraw[];
    const uint32_t smu = s2u(smraw);
    const int tid = threadIdx.x;
    const int bn = blockIdx.x * 128;
    const int bm = blockIdx.y * 128;
    const int z = blockIdx.z;

    const f16 *Bg, *Bu;
    f16* Hout;
    const int* toks = nullptr;
    int cnt = 0;
    if (z == 0) {
        Bg = Bg_all; Bu = Bu_all; Hout = Hs;
    } else {
        const int e = z - 1;
        cnt = g_cnt[e];
        if (bm >= cnt) return;
        toks = g_tok[e];
        Bg = Beg + (size_t)e * 1048576;
        Bu = Beu + (size_t)e * 1048576;
        Hout = Hr + (size_t)e * EPITCH * 1024;
    }

    const int lr = tid >> 3;
    const int lc = tid & 7;
    const int coff = lc * 8;

    const f16 *arp[2], *bgp[2], *bup[2];
    uint32_t dA[2], dBg[2], dBu[2];
#pragma unroll
    for (int i = 0; i < 2; i++) {
        const int r = lr + 64 * i;
        int arow;
        if (z != 0) {
            const int slot = bm + r;
            arow = toks[slot < cnt - 1 ? slot : cnt - 1];
        } else {
            arow = bm + r;
        }
        arp[i] = A  + (size_t)arow * 1024 + coff;
        bgp[i] = Bg + (size_t)(bn + r) * 1024 + coff;
        bup[i] = Bu + (size_t)(bn + r) * 1024 + coff;
        const uint32_t o = (uint32_t)(r * 128 + ((lc ^ (r & 7)) << 4));
        dA[i] = o; dBg[i] = 16384u + o; dBu[i] = 32768u + o;
    }

    const int lane = tid & 31, w = tid >> 5;
    const int m0 = (w & 3) * 32, n0 = (w >> 2) * 32;

    float accG[2][4][4], accU[2][4][4];
#pragma unroll
    for (int mf = 0; mf < 2; mf++)
#pragma unroll
        for (int nf = 0; nf < 4; nf++)
#pragma unroll
            for (int j = 0; j < 4; j++) { accG[mf][nf][j] = 0.f; accU[mf][nf][j] = 0.f; }

#pragma unroll
    for (int st = 0; st < 2; st++) {
        const uint32_t sa = smu + st * GU_STG;
        const int kb = st * 64;
#pragma unroll
        for (int i = 0; i < 2; i++) {
            cp16(sa + dA[i],  arp[i] + kb);
            cp16(sa + dBg[i], bgp[i] + kb);
            cp16(sa + dBu[i], bup[i] + kb);
        }
        cp_commit();
    }

    const int ar_ = lane & 15;
    const int ac_ = lane >> 4;
    const int br_ = (lane & 7) + ((lane >> 4) << 3);
    const int bc_ = (lane >> 3) & 1;

    int stw = 2;
    for (int it = 0; it < 16; ++it) {
        if (it + 2 < 16) {
            const uint32_t sa = smu + stw * GU_STG;
            const int kb = (it + 2) * 64;
#pragma unroll
            for (int i = 0; i < 2; i++) {
                cp16(sa + dA[i],  arp[i] + kb);
                cp16(sa + dBg[i], bgp[i] + kb);
                cp16(sa + dBu[i], bup[i] + kb);
            }
            stw = (stw + 1) == 3 ? 0 : stw + 1;
        }
        cp_commit();
        cp_wait2();
        __syncthreads();

        const uint32_t sa = smu + (it % 3) * GU_STG;
        const uint32_t sg = sa + 16384u, su = sa + 32768u;
#pragma unroll
        for (int s = 0; s < 4; s++) {
            uint32_t av[2][4];
#pragma unroll
            for (int mf = 0; mf < 2; mf++) {
                const int r = m0 + mf * 16 + ar_;
                const int c = s * 2 + ac_;
                ldsm4(av[mf], sa + r * 128 + ((c ^ (r & 7)) << 4));
            }
            {
                uint32_t bv[2][4];
#pragma unroll
                for (int bi = 0; bi < 2; bi++) {
                    const int nr = n0 + bi * 16 + br_;
                    const int c = s * 2 + bc_;
                    ldsm4(bv[bi], sg + nr * 128 + ((c ^ (nr & 7)) << 4));
                }
#pragma unroll
                for (int mf = 0; mf < 2; mf++)
#pragma unroll
                    for (int nf = 0; nf < 4; nf++)
                        mma_f16(accG[mf][nf], av[mf], &bv[nf >> 1][(nf & 1) * 2]);
            }
            {
                uint32_t bv[2][4];
#pragma unroll
                for (int bi = 0; bi < 2; bi++) {
                    const int nr = n0 + bi * 16 + br_;
                    const int c = s * 2 + bc_;
                    ldsm4(bv[bi], su + nr * 128 + ((c ^ (nr & 7)) << 4));
                }
#pragma unroll
                for (int mf = 0; mf < 2; mf++)
#pragma unroll
                    for (int nf = 0; nf < 4; nf++)
                        mma_f16(accU[mf][nf], av[mf], &bv[nf >> 1][(nf & 1) * 2]);
            }
        }
        __syncthreads();
    }

    const int mr = lane >> 2, nc2 = (lane & 3) * 2;
#pragma unroll
    for (int mf = 0; mf < 2; mf++)
#pragma unroll
        for (int nf = 0; nf < 4; nf++)
#pragma unroll
            for (int h = 0; h < 2; h++) {
                const int rl = m0 + mf * 16 + mr + h * 8;
                const int col = bn + n0 + nf * 8 + nc2;
                const float g0 = accG[mf][nf][h * 2], g1 = accG[mf][nf][h * 2 + 1];
                const float u0 = accU[mf][nf][h * 2], u1 = accU[mf][nf][h * 2 + 1];
                const float v0 = u0 / (1.f + __expf(-g0));
                const float v1 = u1 / (1.f + __expf(-g1));
                *reinterpret_cast<uint32_t*>(Hout + (size_t)(bm + rl) * 1024 + col) =
                    packh2(v0, v1);
            }
}

// ---------------------------------------------------------------------------
// Down GEMM with fragment double-buffering. 256 threads, warp tile 32x64,
// BK=64, 16 iters, 3-stage smem pipeline + 2-deep register pipeline.
// ---------------------------------------------------------------------------
#define DN_STG   32768
#define DN_SMEM  (3 * DN_STG)

__global__ void __launch_bounds__(256)
k_down(const f16* __restrict__ As, const f16* __restrict__ Ar,
       const f16* __restrict__ Bs, const f16* __restrict__ Be,
       const float* __restrict__ X, float* __restrict__ out, float* __restrict__ rout)
{
    extern __shared__ char smraw[];
    const uint32_t smu = s2u(smraw);
    const int tid = threadIdx.x;
    const int bn = blockIdx.x * 128;
    const int bm = blockIdx.y * 128;
    const int z = blockIdx.z;

    const f16 *A, *B;
    size_t obase = 0;
    if (z == 0) {
        A = As; B = Bs;
    } else {
        const int e = z - 1;
        if (bm >= g_cnt[e]) return;
        obase = (size_t)e * EPITCH;
        A = Ar + obase * 1024;
        B = Be + (size_t)e * 1048576;
    }

    const int lr = tid >> 3;
    const int lc = tid & 7;
    const int coff = lc * 8;

    const f16 *arp[4], *brp[4];
    uint32_t dA[4], dB[4];
#pragma unroll
    for (int i = 0; i < 4; i++) {
        const int r = lr + 32 * i;
        arp[i] = A + (size_t)(bm + r) * 1024 + coff;
        brp[i] = B + (size_t)(bn + r) * 1024 + coff;
        const uint32_t o = (uint32_t)(r * 128 + ((lc ^ (r & 7)) << 4));
        dA[i] = o; dB[i] = 16384u + o;
    }

    const int lane = tid & 31, w = tid >> 5;
    const int m0 = (w & 3) * 32, n0 = (w >> 2) * 64;

    float acc[2][8][4];
#pragma unroll
    for (int mf = 0; mf < 2; mf++)
#pragma unroll
        for (int nf = 0; nf < 8; nf++)
#pragma unroll
            for (int j = 0; j < 4; j++) acc[mf][nf][j] = 0.f;

#pragma unroll
    for (int st = 0; st < 2; st++) {
        const uint32_t sa = smu + st * DN_STG;
        const int kb = st * 64;
#pragma unroll
        for (int i = 0; i < 4; i++) { cp16(sa + dA[i], arp[i] + kb); cp16(sa + dB[i], brp[i] + kb); }
        cp_commit();
    }

    const int ar_ = lane & 15;
    const int ac_ = lane >> 4;
    const int br_ = (lane & 7) + ((lane >> 4) << 3);
    const int bc_ = (lane >> 3) & 1;

    int stw = 2;
    for (int it = 0; it < 16; ++it) {
        if (it + 2 < 16) {
            const uint32_t sa = smu + stw * DN_STG;
            const int kb = (it + 2) * 64;
#pragma unroll
            for (int i = 0; i < 4; i++) { cp16(sa + dA[i], arp[i] + kb); cp16(sa + dB[i], brp[i] + kb); }
            cp_commit();
            stw = (stw + 1) == 3 ? 0 : stw + 1;
        } else {
            cp_commit();
        }
        cp_wait2();
        __syncthreads();

        const uint32_t sa = smu + (it % 3) * DN_STG;
        const uint32_t sb = sa + 16384u;

        // register-pipelined fragment loads: double-buffered over k16 steps
        uint32_t av[2][2][4], bv[2][4][4];
#pragma unroll
        for (int mf = 0; mf < 2; mf++) {
            const int r = m0 + mf * 16 + ar_;
            ldsm4(av[0][mf], sa + r * 128 + ((ac_ ^ (r & 7)) << 4));
        }
#pragma unroll
        for (int bi = 0; bi < 4; bi++) {
            const int nr = n0 + bi * 16 + br_;
            ldsm4(bv[0][bi], sb + nr * 128 + ((bc_ ^ (nr & 7)) << 4));
        }
#pragma unroll
        for (int s = 0; s < 4; s++) {
            const int p = s & 1;
            if (s < 3) {
                const int c = (s + 1) * 2;
#pragma unroll
                for (int mf = 0; mf < 2; mf++) {
                    const int r = m0 + mf * 16 + ar_;
                    ldsm4(av[p ^ 1][mf], sa + r * 128 + (((c + ac_) ^ (r & 7)) << 4));
                }
#pragma unroll
                for (int bi = 0; bi < 4; bi++) {
                    const int nr = n0 + bi * 16 + br_;
                    ldsm4(bv[p ^ 1][bi], sb + nr * 128 + (((c + bc_) ^ (nr & 7)) << 4));
                }
            }
#pragma unroll
            for (int mf = 0; mf < 2; mf++)
#pragma unroll
                for (int nf = 0; nf < 8; nf++)
                    mma_f16(acc[mf][nf], av[p][mf], &bv[p][nf >> 1][(nf & 1) * 2]);
        }
        __syncthreads();
    }

    const int mr = lane >> 2, nc2 = (lane & 3) * 2;
#pragma unroll
    for (int mf = 0; mf < 2; mf++)
#pragma unroll
        for (int nf = 0; nf < 8; nf++)
#pragma unroll
            for (int h = 0; h < 2; h++) {
                const int rl = m0 + mf * 16 + mr + h * 8;
                const int col = bn + n0 + nf * 8 + nc2;
                const float c0 = acc[mf][nf][h * 2], c1 = acc[mf][nf][h * 2 + 1];
                if (z == 0) {
                    const int t = bm + rl;
                    const float2 rv = *reinterpret_cast<const float2*>(X + (size_t)t * 1024 + col);
                    float2 v = make_float2(rv.x + c0, rv.y + c1);
                    *reinterpret_cast<float2*>(out + (size_t)t * 1024 + col) = v;
                } else {
                    float2 v = make_float2(c0, c1);
                    *reinterpret_cast<float2*>(rout + (obase + bm + rl) * 1024 + col) = v;
                }
            }
}

// ---------------------------------------------------------------------------
// combine
// ---------------------------------------------------------------------------
__global__ void k_combine(float* __restrict__ out) {
    const int t = blockIdx.x;
    const int e1 = g_sel_e[t * 2],     p1 = g_sel_p[t * 2];
    const int e2 = g_sel_e[t * 2 + 1], p2 = g_sel_p[t * 2 + 1];
    const float w1 = g_sel_w[t * 2], w2 = g_sel_w[t * 2 + 1];
    const float* r1 = g_rout + ((size_t)e1 * EPITCH + p1) * 1024;
    const float* r2 = g_rout + ((size_t)e2 * EPITCH + p2) * 1024;
    float* o = out + (size_t)t * 1024;
#pragma unroll
    for (int k = 0; k < 2; k++) {
        const int j = (threadIdx.x + k * 128) * 4;
        const float4 a = *(const float4*)(r1 + j);
        const float4 b = *(const float4*)(r2 + j);
        float4 v = *(float4*)(o + j);
        v.x += w1 * a.x + w2 * b.x; v.y += w1 * a.y + w2 * b.y;
        v.z += w1 * a.z + w2 * b.z; v.w += w1 * a.w + w2 * b.w;
        *(float4*)(o + j) = v;
    }
}

// ---------------------------------------------------------------------------
// launch
// ---------------------------------------------------------------------------
extern "C" void kernel_launch(void* const* d_in, const int* in_sizes, int n_in,
                              void* d_out, int out_size)
{
    const float* X  = (const float*)d_in[0];
    const float* RW = (const float*)d_in[1];
    const float* SG = (const float*)d_in[2];
    const float* SU = (const float*)d_in[3];
    const float* SD = (const float*)d_in[4];
    const float* EG = (const float*)d_in[5];
    const float* EU = (const float*)d_in[6];
    const float* ED = (const float*)d_in[7];
    float* out = (float*)d_out;

    static bool once = false;
    if (!once) {
        cudaFuncSetAttribute(k_gateup, cudaFuncAttributeMaxDynamicSharedMemorySize, GU_SMEM);
        cudaFuncSetAttribute(k_down,   cudaFuncAttributeMaxDynamicSharedMemorySize, DN_SMEM);
        once = true;
    }

    f16 *xc, *wsg, *wsu, *wsd, *weg, *weu, *wed, *hids, *hidr;
    float *rout;
    cudaGetSymbolAddress((void**)&xc,   g_xc);
    cudaGetSymbolAddress((void**)&wsg,  g_wsg);
    cudaGetSymbolAddress((void**)&wsu,  g_wsu);
    cudaGetSymbolAddress((void**)&wsd,  g_wsd);
    cudaGetSymbolAddress((void**)&weg,  g_weg);
    cudaGetSymbolAddress((void**)&weu,  g_weu);
    cudaGetSymbolAddress((void**)&wed,  g_wed);
    cudaGetSymbolAddress((void**)&hids, g_hid_s);
    cudaGetSymbolAddress((void**)&hidr, g_hid_r);
    cudaGetSymbolAddress((void**)&rout, g_rout);

    k_convw<<<dim3(4, 64, 27), 256>>>(SG, SU, SD, EG, EU, ED,
                                      wsg, wsu, wsd, weg, weu, wed);  // zeroes g_cnt
    k_router<<<1024, 128>>>(X, RW);                                   // + convx fused

    k_gateup<<<dim3(8, 32, 9), 512, GU_SMEM>>>(xc, wsg, wsu, weg, weu, hids, hidr);
    k_down  <<<dim3(8, 32, 9), 256, DN_SMEM>>>(hids, hidr, wsd, wed, X, out, rout);

    k_combine<<<T_TOK, 128>>>(out);
}

// round 17
// speedup vs baseline: 1.0260x; 1.0146x over previous
#include <cuda_runtime.h>
#include <cuda_fp16.h>
#include <math.h>
#include <stdint.h>

// ===========================================================================
// TinyMoE, base-ISA tensor ops (mma.sync fp16 / ldmatrix / cp.async).
// R17: R16 base (303.8us); ONE change: k_gateup A-fragment double-buffering
//      (mirror of the k_down register pipeline that tested positive in R16).
// ===========================================================================

#define T_TOK 4096
#define HD    1024
#define NE    8
#define EPITCH 4096

using f16 = __half;

// ---------------- device scratch -------------------------------------------
__device__ f16   g_xc   [(size_t)T_TOK * 1024];
__device__ f16   g_wsg  [(size_t)1024 * 1024];
__device__ f16   g_wsu  [(size_t)1024 * 1024];
__device__ f16   g_wsd  [(size_t)1024 * 1024];
__device__ f16   g_weg  [(size_t)NE * 1024 * 1024];
__device__ f16   g_weu  [(size_t)NE * 1024 * 1024];
__device__ f16   g_wed  [(size_t)NE * 1024 * 1024];
__device__ f16   g_hid_s[(size_t)T_TOK * 1024];
__device__ f16   g_hid_r[(size_t)NE * EPITCH * 1024];
__device__ float g_rout [(size_t)NE * EPITCH * 1024];
__device__ int   g_cnt[NE];
__device__ int   g_tok[NE][T_TOK];
__device__ int   g_sel_e[T_TOK * 2];
__device__ int   g_sel_p[T_TOK * 2];
__device__ float g_sel_w[T_TOK * 2];

// ---------------- asm helpers ----------------------------------------------
__device__ __forceinline__ uint32_t s2u(const void* p) {
    uint32_t a;
    asm("{ .reg .u64 t; cvta.to.shared.u64 t, %1; cvt.u32.u64 %0, t; }" : "=r"(a) : "l"(p));
    return a;
}
__device__ __forceinline__ void cp16(uint32_t dst, const void* src) {
    asm volatile("cp.async.cg.shared.global [%0], [%1], 16;" :: "r"(dst), "l"(src));
}
__device__ __forceinline__ void cp_commit() { asm volatile("cp.async.commit_group;"); }
__device__ __forceinline__ void cp_wait2()  { asm volatile("cp.async.wait_group 2;"); }
__device__ __forceinline__ void ldsm4(uint32_t* r, uint32_t addr) {
    asm volatile("ldmatrix.sync.aligned.m8n8.x4.shared.b16 {%0,%1,%2,%3}, [%4];"
        : "=r"(r[0]), "=r"(r[1]), "=r"(r[2]), "=r"(r[3]) : "r"(addr));
}
__device__ __forceinline__ void mma_f16(float* c, const uint32_t* a, const uint32_t* b) {
    asm volatile(
        "mma.sync.aligned.m16n8k16.row.col.f32.f16.f16.f32 "
        "{%0,%1,%2,%3}, {%4,%5,%6,%7}, {%8,%9}, {%0,%1,%2,%3};"
        : "+f"(c[0]), "+f"(c[1]), "+f"(c[2]), "+f"(c[3])
        : "r"(a[0]), "r"(a[1]), "r"(a[2]), "r"(a[3]), "r"(b[0]), "r"(b[1]));
}
__device__ __forceinline__ uint32_t packh2(float a, float b) {
    f16 h0 = __float2half_rn(a), h1 = __float2half_rn(b);
    return (uint32_t)*(uint16_t*)&h0 | ((uint32_t)*(uint16_t*)&h1 << 16);
}

// ---------------------------------------------------------------------------
// convw: smem-free transpose-convert; block (0,0,0) zeroes g_cnt
// ---------------------------------------------------------------------------
__global__ void __launch_bounds__(256)
k_convw(const float* __restrict__ SG, const float* __restrict__ SU,
        const float* __restrict__ SD, const float* __restrict__ EG,
        const float* __restrict__ EU, const float* __restrict__ ED,
        f16* __restrict__ wsg, f16* __restrict__ wsu, f16* __restrict__ wsd,
        f16* __restrict__ weg, f16* __restrict__ weu, f16* __restrict__ wed)
{
    if (blockIdx.x == 0 && blockIdx.y == 0 && blockIdx.z == 0 && threadIdx.x < NE)
        g_cnt[threadIdx.x] = 0;

    const int z = blockIdx.z;
    const float* src;
    f16* dst;
    if      (z == 0) { src = SG; dst = wsg; }
    else if (z == 1) { src = SU; dst = wsu; }
    else if (z == 2) { src = SD; dst = wsd; }
    else if (z < 11) { src = EG + (size_t)(z - 3)  * 1048576; dst = weg + (size_t)(z - 3)  * 1048576; }
    else if (z < 19) { src = EU + (size_t)(z - 11) * 1048576; dst = weu + (size_t)(z - 11) * 1048576; }
    else             { src = ED + (size_t)(z - 19) * 1048576; dst = wed + (size_t)(z - 19) * 1048576; }

    const int n  = blockIdx.x * 256 + threadIdx.x;
    const int k0 = blockIdx.y * 16;
    float v[16];
#pragma unroll
    for (int kk = 0; kk < 16; kk++)
        v[kk] = src[(size_t)(k0 + kk) * 1024 + n];
    uint4 a, b;
    a.x = packh2(v[0],  v[1]);  a.y = packh2(v[2],  v[3]);
    a.z = packh2(v[4],  v[5]);  a.w = packh2(v[6],  v[7]);
    b.x = packh2(v[8],  v[9]);  b.y = packh2(v[10], v[11]);
    b.z = packh2(v[12], v[13]); b.w = packh2(v[14], v[15]);
    f16* drow = dst + (size_t)n * 1024 + k0;
    *reinterpret_cast<uint4*>(drow)     = a;
    *reinterpret_cast<uint4*>(drow + 8) = b;
}

// ---------------------------------------------------------------------------
// router + fused convx
// ---------------------------------------------------------------------------
__global__ void k_router(const float* __restrict__ X, const float* __restrict__ RW) {
    const int t = (blockIdx.x * blockDim.x + threadIdx.x) >> 5;
    const int lane = threadIdx.x & 31;
    if (t >= T_TOK) return;
    const float4* xr = reinterpret_cast<const float4*>(X + (size_t)t * HD);
    float acc[NE];
#pragma unroll
    for (int e = 0; e < NE; e++) acc[e] = 0.f;
#pragma unroll
    for (int i = 0; i < 8; i++) {
        const float4 xv = xr[i * 32 + lane];
        const uint2 hp = make_uint2(packh2(xv.x, xv.y), packh2(xv.z, xv.w));
        *reinterpret_cast<uint2*>(g_xc + (size_t)t * HD + (i * 32 + lane) * 4) = hp;
#pragma unroll
        for (int e = 0; e < NE; e++) {
            const float4 wv = *reinterpret_cast<const float4*>(
                RW + (size_t)e * HD + i * 128 + lane * 4);
            acc[e] += xv.x * wv.x + xv.y * wv.y + xv.z * wv.z + xv.w * wv.w;
        }
    }
#pragma unroll
    for (int e = 0; e < NE; e++)
#pragma unroll
        for (int off = 16; off > 0; off >>= 1)
            acc[e] += __shfl_down_sync(0xffffffffu, acc[e], off);
    if (lane == 0) {
        float m = acc[0];
#pragma unroll
        for (int e = 1; e < NE; e++) m = fmaxf(m, acc[e]);
        float p[NE], s = 0.f;
#pragma unroll
        for (int e = 0; e < NE; e++) { p[e] = expf(acc[e] - m); s += p[e]; }
        const float inv = 1.f / s;
#pragma unroll
        for (int e = 0; e < NE; e++) p[e] *= inv;
        int i1 = 0; float b1 = p[0];
#pragma unroll
        for (int e = 1; e < NE; e++) if (p[e] > b1) { b1 = p[e]; i1 = e; }
        int i2 = -1; float b2 = -1.f;
#pragma unroll
        for (int e = 0; e < NE; e++) if (e != i1 && p[e] > b2) { b2 = p[e]; i2 = e; }
        int pos = atomicAdd(&g_cnt[i1], 1);
        g_tok[i1][pos] = t;
        g_sel_e[t * 2] = i1; g_sel_p[t * 2] = pos; g_sel_w[t * 2] = b1;
        pos = atomicAdd(&g_cnt[i2], 1);
        g_tok[i2][pos] = t;
        g_sel_e[t * 2 + 1] = i2; g_sel_p[t * 2 + 1] = pos; g_sel_w[t * 2 + 1] = b2;
    }
}

// ---------------------------------------------------------------------------
// Fused gate+up GEMM + SwiGLU. 512 threads, warp tile 32x32 per matrix.
// BK=64, 16 iters, 3-stage smem pipeline + A-fragment register pipeline.
// ---------------------------------------------------------------------------
#define GU_STG   49152
#define GU_SMEM  (3 * GU_STG)

__global__ void __launch_bounds__(512)
k_gateup(const f16* __restrict__ A, const f16* __restrict__ Bg_all,
         const f16* __restrict__ Bu_all, const f16* __restrict__ Beg,
         const f16* __restrict__ Beu, f16* __restrict__ Hs, f16* __restrict__ Hr)
{
    extern __shared__ char smraw[];
    const uint32_t smu = s2u(smraw);
    const int tid = threadIdx.x;
    const int bn = blockIdx.x * 128;
    const int bm = blockIdx.y * 128;
    const int z = blockIdx.z;

    const f16 *Bg, *Bu;
    f16* Hout;
    const int* toks = nullptr;
    int cnt = 0;
    if (z == 0) {
        Bg = Bg_all; Bu = Bu_all; Hout = Hs;
    } else {
        const int e = z - 1;
        cnt = g_cnt[e];
        if (bm >= cnt) return;
        toks = g_tok[e];
        Bg = Beg + (size_t)e * 1048576;
        Bu = Beu + (size_t)e * 1048576;
        Hout = Hr + (size_t)e * EPITCH * 1024;
    }

    const int lr = tid >> 3;
    const int lc = tid & 7;
    const int coff = lc * 8;

    const f16 *arp[2], *bgp[2], *bup[2];
    uint32_t dA[2], dBg[2], dBu[2];
#pragma unroll
    for (int i = 0; i < 2; i++) {
        const int r = lr + 64 * i;
        int arow;
        if (z != 0) {
            const int slot = bm + r;
            arow = toks[slot < cnt - 1 ? slot : cnt - 1];
        } else {
            arow = bm + r;
        }
        arp[i] = A  + (size_t)arow * 1024 + coff;
        bgp[i] = Bg + (size_t)(bn + r) * 1024 + coff;
        bup[i] = Bu + (size_t)(bn + r) * 1024 + coff;
        const uint32_t o = (uint32_t)(r * 128 + ((lc ^ (r & 7)) << 4));
        dA[i] = o; dBg[i] = 16384u + o; dBu[i] = 32768u + o;
    }

    const int lane = tid & 31, w = tid >> 5;
    const int m0 = (w & 3) * 32, n0 = (w >> 2) * 32;

    float accG[2][4][4], accU[2][4][4];
#pragma unroll
    for (int mf = 0; mf < 2; mf++)
#pragma unroll
        for (int nf = 0; nf < 4; nf++)
#pragma unroll
            for (int j = 0; j < 4; j++) { accG[mf][nf][j] = 0.f; accU[mf][nf][j] = 0.f; }

#pragma unroll
    for (int st = 0; st < 2; st++) {
        const uint32_t sa = smu + st * GU_STG;
        const int kb = st * 64;
#pragma unroll
        for (int i = 0; i < 2; i++) {
            cp16(sa + dA[i],  arp[i] + kb);
            cp16(sa + dBg[i], bgp[i] + kb);
            cp16(sa + dBu[i], bup[i] + kb);
        }
        cp_commit();
    }

    const int ar_ = lane & 15;
    const int ac_ = lane >> 4;
    const int br_ = (lane & 7) + ((lane >> 4) << 3);
    const int bc_ = (lane >> 3) & 1;

    int stw = 2;
    for (int it = 0; it < 16; ++it) {
        if (it + 2 < 16) {
            const uint32_t sa = smu + stw * GU_STG;
            const int kb = (it + 2) * 64;
#pragma unroll
            for (int i = 0; i < 2; i++) {
                cp16(sa + dA[i],  arp[i] + kb);
                cp16(sa + dBg[i], bgp[i] + kb);
                cp16(sa + dBu[i], bup[i] + kb);
            }
            stw = (stw + 1) == 3 ? 0 : stw + 1;
        }
        cp_commit();
        cp_wait2();
        __syncthreads();

        const uint32_t sa = smu + (it % 3) * GU_STG;
        const uint32_t sg = sa + 16384u, su = sa + 32768u;

        // A-fragment register pipeline (double-buffered across k16 steps)
        uint32_t av[2][2][4];
#pragma unroll
        for (int mf = 0; mf < 2; mf++) {
            const int r = m0 + mf * 16 + ar_;
            ldsm4(av[0][mf], sa + r * 128 + ((ac_ ^ (r & 7)) << 4));
        }
#pragma unroll
        for (int s = 0; s < 4; s++) {
            const int p = s & 1;
            if (s < 3) {
                const int c = (s + 1) * 2;
#pragma unroll
                for (int mf = 0; mf < 2; mf++) {
                    const int r = m0 + mf * 16 + ar_;
                    ldsm4(av[p ^ 1][mf], sa + r * 128 + (((c + ac_) ^ (r & 7)) << 4));
                }
            }
            {
                uint32_t bv[2][4];
#pragma unroll
                for (int bi = 0; bi < 2; bi++) {
                    const int nr = n0 + bi * 16 + br_;
                    const int c = s * 2 + bc_;
                    ldsm4(bv[bi], sg + nr * 128 + ((c ^ (nr & 7)) << 4));
                }
#pragma unroll
                for (int mf = 0; mf < 2; mf++)
#pragma unroll
                    for (int nf = 0; nf < 4; nf++)
                        mma_f16(accG[mf][nf], av[p][mf], &bv[nf >> 1][(nf & 1) * 2]);
            }
            {
                uint32_t bv[2][4];
#pragma unroll
                for (int bi = 0; bi < 2; bi++) {
                    const int nr = n0 + bi * 16 + br_;
                    const int c = s * 2 + bc_;
                    ldsm4(bv[bi], su + nr * 128 + ((c ^ (nr & 7)) << 4));
                }
#pragma unroll
                for (int mf = 0; mf < 2; mf++)
#pragma unroll
                    for (int nf = 0; nf < 4; nf++)
                        mma_f16(accU[mf][nf], av[p][mf], &bv[nf >> 1][(nf & 1) * 2]);
            }
        }
        __syncthreads();
    }

    const int mr = lane >> 2, nc2 = (lane & 3) * 2;
#pragma unroll
    for (int mf = 0; mf < 2; mf++)
#pragma unroll
        for (int nf = 0; nf < 4; nf++)
#pragma unroll
            for (int h = 0; h < 2; h++) {
                const int rl = m0 + mf * 16 + mr + h * 8;
                const int col = bn + n0 + nf * 8 + nc2;
                const float g0 = accG[mf][nf][h * 2], g1 = accG[mf][nf][h * 2 + 1];
                const float u0 = accU[mf][nf][h * 2], u1 = accU[mf][nf][h * 2 + 1];
                const float v0 = u0 / (1.f + __expf(-g0));
                const float v1 = u1 / (1.f + __expf(-g1));
                *reinterpret_cast<uint32_t*>(Hout + (size_t)(bm + rl) * 1024 + col) =
                    packh2(v0, v1);
            }
}

// ---------------------------------------------------------------------------
// Down GEMM (R16, unchanged): fragment double-buffered, 256 threads,
// warp tile 32x64, BK=64, 3-stage smem pipeline.
// ---------------------------------------------------------------------------
#define DN_STG   32768
#define DN_SMEM  (3 * DN_STG)

__global__ void __launch_bounds__(256)
k_down(const f16* __restrict__ As, const f16* __restrict__ Ar,
       const f16* __restrict__ Bs, const f16* __restrict__ Be,
       const float* __restrict__ X, float* __restrict__ out, float* __restrict__ rout)
{
    extern __shared__ char smraw[];
    const uint32_t smu = s2u(smraw);
    const int tid = threadIdx.x;
    const int bn = blockIdx.x * 128;
    const int bm = blockIdx.y * 128;
    const int z = blockIdx.z;

    const f16 *A, *B;
    size_t obase = 0;
    if (z == 0) {
        A = As; B = Bs;
    } else {
        const int e = z - 1;
        if (bm >= g_cnt[e]) return;
        obase = (size_t)e * EPITCH;
        A = Ar + obase * 1024;
        B = Be + (size_t)e * 1048576;
    }

    const int lr = tid >> 3;
    const int lc = tid & 7;
    const int coff = lc * 8;

    const f16 *arp[4], *brp[4];
    uint32_t dA[4], dB[4];
#pragma unroll
    for (int i = 0; i < 4; i++) {
        const int r = lr + 32 * i;
        arp[i] = A + (size_t)(bm + r) * 1024 + coff;
        brp[i] = B + (size_t)(bn + r) * 1024 + coff;
        const uint32_t o = (uint32_t)(r * 128 + ((lc ^ (r & 7)) << 4));
        dA[i] = o; dB[i] = 16384u + o;
    }

    const int lane = tid & 31, w = tid >> 5;
    const int m0 = (w & 3) * 32, n0 = (w >> 2) * 64;

    float acc[2][8][4];
#pragma unroll
    for (int mf = 0; mf < 2; mf++)
#pragma unroll
        for (int nf = 0; nf < 8; nf++)
#pragma unroll
            for (int j = 0; j < 4; j++) acc[mf][nf][j] = 0.f;

#pragma unroll
    for (int st = 0; st < 2; st++) {
        const uint32_t sa = smu + st * DN_STG;
        const int kb = st * 64;
#pragma unroll
        for (int i = 0; i < 4; i++) { cp16(sa + dA[i], arp[i] + kb); cp16(sa + dB[i], brp[i] + kb); }
        cp_commit();
    }

    const int ar_ = lane & 15;
    const int ac_ = lane >> 4;
    const int br_ = (lane & 7) + ((lane >> 4) << 3);
    const int bc_ = (lane >> 3) & 1;

    int stw = 2;
    for (int it = 0; it < 16; ++it) {
        if (it + 2 < 16) {
            const uint32_t sa = smu + stw * DN_STG;
            const int kb = (it + 2) * 64;
#pragma unroll
            for (int i = 0; i < 4; i++) { cp16(sa + dA[i], arp[i] + kb); cp16(sa + dB[i], brp[i] + kb); }
            cp_commit();
            stw = (stw + 1) == 3 ? 0 : stw + 1;
        } else {
            cp_commit();
        }
        cp_wait2();
        __syncthreads();

        const uint32_t sa = smu + (it % 3) * DN_STG;
        const uint32_t sb = sa + 16384u;

        uint32_t av[2][2][4], bv[2][4][4];
#pragma unroll
        for (int mf = 0; mf < 2; mf++) {
            const int r = m0 + mf * 16 + ar_;
            ldsm4(av[0][mf], sa + r * 128 + ((ac_ ^ (r & 7)) << 4));
        }
#pragma unroll
        for (int bi = 0; bi < 4; bi++) {
            const int nr = n0 + bi * 16 + br_;
            ldsm4(bv[0][bi], sb + nr * 128 + ((bc_ ^ (nr & 7)) << 4));
        }
#pragma unroll
        for (int s = 0; s < 4; s++) {
            const int p = s & 1;
            if (s < 3) {
                const int c = (s + 1) * 2;
#pragma unroll
                for (int mf = 0; mf < 2; mf++) {
                    const int r = m0 + mf * 16 + ar_;
                    ldsm4(av[p ^ 1][mf], sa + r * 128 + (((c + ac_) ^ (r & 7)) << 4));
                }
#pragma unroll
                for (int bi = 0; bi < 4; bi++) {
                    const int nr = n0 + bi * 16 + br_;
                    ldsm4(bv[p ^ 1][bi], sb + nr * 128 + (((c + bc_) ^ (nr & 7)) << 4));
                }
            }
#pragma unroll
            for (int mf = 0; mf < 2; mf++)
#pragma unroll
                for (int nf = 0; nf < 8; nf++)
                    mma_f16(acc[mf][nf], av[p][mf], &bv[p][nf >> 1][(nf & 1) * 2]);
        }
        __syncthreads();
    }

    const int mr = lane >> 2, nc2 = (lane & 3) * 2;
#pragma unroll
    for (int mf = 0; mf < 2; mf++)
#pragma unroll
        for (int nf = 0; nf < 8; nf++)
#pragma unroll
            for (int h = 0; h < 2; h++) {
                const int rl = m0 + mf * 16 + mr + h * 8;
                const int col = bn + n0 + nf * 8 + nc2;
                const float c0 = acc[mf][nf][h * 2], c1 = acc[mf][nf][h * 2 + 1];
                if (z == 0) {
                    const int t = bm + rl;
                    const float2 rv = *reinterpret_cast<const float2*>(X + (size_t)t * 1024 + col);
                    float2 v = make_float2(rv.x + c0, rv.y + c1);
                    *reinterpret_cast<float2*>(out + (size_t)t * 1024 + col) = v;
                } else {
                    float2 v = make_float2(c0, c1);
                    *reinterpret_cast<float2*>(rout + (obase + bm + rl) * 1024 + col) = v;
                }
            }
}

// ---------------------------------------------------------------------------
// combine
// ---------------------------------------------------------------------------
__global__ void k_combine(float* __restrict__ out) {
    const int t = blockIdx.x;
    const int e1 = g_sel_e[t * 2],     p1 = g_sel_p[t * 2];
    const int e2 = g_sel_e[t * 2 + 1], p2 = g_sel_p[t * 2 + 1];
    const float w1 = g_sel_w[t * 2], w2 = g_sel_w[t * 2 + 1];
    const float* r1 = g_rout + ((size_t)e1 * EPITCH + p1) * 1024;
    const float* r2 = g_rout + ((size_t)e2 * EPITCH + p2) * 1024;
    float* o = out + (size_t)t * 1024;
#pragma unroll
    for (int k = 0; k < 2; k++) {
        const int j = (threadIdx.x + k * 128) * 4;
        const float4 a = *(const float4*)(r1 + j);
        const float4 b = *(const float4*)(r2 + j);
        float4 v = *(float4*)(o + j);
        v.x += w1 * a.x + w2 * b.x; v.y += w1 * a.y + w2 * b.y;
        v.z += w1 * a.z + w2 * b.z; v.w += w1 * a.w + w2 * b.w;
        *(float4*)(o + j) = v;
    }
}

// ---------------------------------------------------------------------------
// launch
// ---------------------------------------------------------------------------
extern "C" void kernel_launch(void* const* d_in, const int* in_sizes, int n_in,
                              void* d_out, int out_size)
{
    const float* X  = (const float*)d_in[0];
    const float* RW = (const float*)d_in[1];
    const float* SG = (const float*)d_in[2];
    const float* SU = (const float*)d_in[3];
    const float* SD = (const float*)d_in[4];
    const float* EG = (const float*)d_in[5];
    const float* EU = (const float*)d_in[6];
    const float* ED = (const float*)d_in[7];
    float* out = (float*)d_out;

    static bool once = false;
    if (!once) {
        cudaFuncSetAttribute(k_gateup, cudaFuncAttributeMaxDynamicSharedMemorySize, GU_SMEM);
        cudaFuncSetAttribute(k_down,   cudaFuncAttributeMaxDynamicSharedMemorySize, DN_SMEM);
        once = true;
    }

    f16 *xc, *wsg, *wsu, *wsd, *weg, *weu, *wed, *hids, *hidr;
    float *rout;
    cudaGetSymbolAddress((void**)&xc,   g_xc);
    cudaGetSymbolAddress((void**)&wsg,  g_wsg);
    cudaGetSymbolAddress((void**)&wsu,  g_wsu);
    cudaGetSymbolAddress((void**)&wsd,  g_wsd);
    cudaGetSymbolAddress((void**)&weg,  g_weg);
    cudaGetSymbolAddress((void**)&weu,  g_weu);
    cudaGetSymbolAddress((void**)&wed,  g_wed);
    cudaGetSymbolAddress((void**)&hids, g_hid_s);
    cudaGetSymbolAddress((void**)&hidr, g_hid_r);
    cudaGetSymbolAddress((void**)&rout, g_rout);

    k_convw<<<dim3(4, 64, 27), 256>>>(SG, SU, SD, EG, EU, ED,
                                      wsg, wsu, wsd, weg, weu, wed);  // zeroes g_cnt
    k_router<<<1024, 128>>>(X, RW);                                   // + convx fused

    k_gateup<<<dim3(8, 32, 9), 512, GU_SMEM>>>(xc, wsg, wsu, weg, weu, hids, hidr);
    k_down  <<<dim3(8, 32, 9), 256, DN_SMEM>>>(hids, hidr, wsd, wed, X, out, rout);

    k_combine<<<T_TOK, 128>>>(out);
}